// round 8
// baseline (speedup 1.0000x reference)
#include <cuda_runtime.h>

#define BTOT 16384
#define TENC 256
#define NIN 6
#define GROUPS 8
#define RR 14
#define ROWS (GROUPS * RR)          /* 112 rows per block */
#define NTHREADS 512
#define NBLOCKS ((BTOT + ROWS - 1) / ROWS)   /* 147 */

typedef unsigned long long u64;

/* ---------------- shared memory layout (float offsets) ---------------- */
#define SZW (3 * 64 * 68)           /* one 192x64 matrix, pitch-68 padded */
#define OFF_WHH0 0
#define OFF_WIH1 (SZW)
#define OFF_WHH1 (2 * SZW)
#define OFF_WIH0 (3 * SZW)          /* enc: [3][6][64]=1152 ; dec: [192]  */
#define OFF_BIH0 (OFF_WIH0 + 1152)
#define OFF_BHH0 (OFF_BIH0 + 192)
#define OFF_BIH1 (OFF_BHH0 + 192)
#define OFF_BHH1 (OFF_BIH1 + 192)
#define OFF_WON  (OFF_BHH1 + 192)
#define OFF_WCV  (OFF_WON + 64)
#define OFF_BON  (OFF_WCV + 64)
#define OFF_BCV  (OFF_BON + 1)
#define OFF_H0   ((OFF_BCV + 1 + 3) & ~3)   /* 16B-aligned for ulonglong2 */
#define OFF_H1   (OFF_H0 + ROWS * 64)
#define OFF_XS   (OFF_H1 + ROWS * 64)
#define OFF_PREV (OFF_XS + ROWS * 8)
#define OFF_RED  (OFF_PREV + ROWS)
#define SMEM_FLOATS (OFF_RED + GROUPS * 2 * 2 * RR)
#define SMEM_BYTES (SMEM_FLOATS * 4)

/* packed 2-wide fp32 FMA (SASS FFMA2) */
__device__ __forceinline__ void f2acc(u64& acc, u64 a, u64 b) {
    asm("fma.rn.f32x2 %0, %1, %2, %0;" : "+l"(acc) : "l"(a), "l"(b));
}
__device__ __forceinline__ float f2red(u64 v) {
    return __uint_as_float((unsigned)v) + __uint_as_float((unsigned)(v >> 32));
}

/* single-MUFU tanh; sigmoid via tanh identity */
__device__ __forceinline__ float tanhf_(float x) {
    float y; asm("tanh.approx.f32 %0, %1;" : "=f"(y) : "f"(x)); return y;
}
__device__ __forceinline__ float sigf(float x) {
    return fmaf(tanhf_(0.5f * x), 0.5f, 0.5f);
}

/* ---- layer0 recurrent matmul, pass 1 (r,z gates), packed over k ---- */
#define L0_PASS1(HB)                                                            \
    do {                                                                        \
        _Pragma("unroll 2")                                                     \
        for (int kk = 0; kk < 64; kk += 4) {                                    \
            const ulonglong2 wr = *(const ulonglong2*)&sm[OFF_WHH0 + j * 68 + kk];        \
            const ulonglong2 wz = *(const ulonglong2*)&sm[OFF_WHH0 + (64 + j) * 68 + kk]; \
            _Pragma("unroll")                                                   \
            for (int r = 0; r < RR; r++) {                                      \
                const ulonglong2 hv = *(const ulonglong2*)&(HB)[r * 64 + kk];   \
                f2acc(pr[r], wr.x, hv.x); f2acc(pr[r], wr.y, hv.y);             \
                f2acc(pz[r], wz.x, hv.x); f2acc(pz[r], wz.y, hv.y);             \
            }                                                                   \
        }                                                                       \
    } while (0)

/* ---- layer0 recurrent matmul, pass 2 (n gate) ---- */
#define L0_PASS2(HB)                                                            \
    do {                                                                        \
        _Pragma("unroll 2")                                                     \
        for (int kk = 0; kk < 64; kk += 4) {                                    \
            const ulonglong2 wn = *(const ulonglong2*)&sm[OFF_WHH0 + (128 + j) * 68 + kk];\
            _Pragma("unroll")                                                   \
            for (int r = 0; r < RR; r++) {                                      \
                const ulonglong2 hv = *(const ulonglong2*)&(HB)[r * 64 + kk];   \
                f2acc(pn[r], wn.x, hv.x); f2acc(pn[r], wn.y, hv.y);             \
            }                                                                   \
        }                                                                       \
    } while (0)

/* ---- layer1 fused (Wih1@h0 + Whh1@h1), pass 1 (r,z) ---- */
#define L1_PASS1()                                                              \
    do {                                                                        \
        _Pragma("unroll 2")                                                     \
        for (int kk = 0; kk < 64; kk += 4) {                                    \
            const ulonglong2 iwr = *(const ulonglong2*)&sm[OFF_WIH1 + j * 68 + kk];        \
            const ulonglong2 iwz = *(const ulonglong2*)&sm[OFF_WIH1 + (64 + j) * 68 + kk]; \
            const ulonglong2 hwr = *(const ulonglong2*)&sm[OFF_WHH1 + j * 68 + kk];        \
            const ulonglong2 hwz = *(const ulonglong2*)&sm[OFF_WHH1 + (64 + j) * 68 + kk]; \
            _Pragma("unroll")                                                   \
            for (int r = 0; r < RR; r++) {                                      \
                const ulonglong2 av = *(const ulonglong2*)&h0b[r * 64 + kk];    \
                const ulonglong2 bv = *(const ulonglong2*)&h1b[r * 64 + kk];    \
                f2acc(pr[r], iwr.x, av.x); f2acc(pr[r], iwr.y, av.y);           \
                f2acc(pr[r], hwr.x, bv.x); f2acc(pr[r], hwr.y, bv.y);           \
                f2acc(pz[r], iwz.x, av.x); f2acc(pz[r], iwz.y, av.y);           \
                f2acc(pz[r], hwz.x, bv.x); f2acc(pz[r], hwz.y, bv.y);           \
            }                                                                   \
        }                                                                       \
    } while (0)

/* ---- layer1 fused, pass 2 (n: ani from Wih1@h0, anh from Whh1@h1) ---- */
#define L1_PASS2()                                                              \
    do {                                                                        \
        _Pragma("unroll 2")                                                     \
        for (int kk = 0; kk < 64; kk += 4) {                                    \
            const ulonglong2 iwn = *(const ulonglong2*)&sm[OFF_WIH1 + (128 + j) * 68 + kk];\
            const ulonglong2 hwn = *(const ulonglong2*)&sm[OFF_WHH1 + (128 + j) * 68 + kk];\
            _Pragma("unroll")                                                   \
            for (int r = 0; r < RR; r++) {                                      \
                const ulonglong2 av = *(const ulonglong2*)&h0b[r * 64 + kk];    \
                const ulonglong2 bv = *(const ulonglong2*)&h1b[r * 64 + kk];    \
                f2acc(pni[r], iwn.x, av.x); f2acc(pni[r], iwn.y, av.y);         \
                f2acc(pnh[r], hwn.x, bv.x); f2acc(pnh[r], hwn.y, bv.y);         \
            }                                                                   \
        }                                                                       \
    } while (0)

__global__ void __launch_bounds__(NTHREADS, 1)
ccseq_kernel(const float* __restrict__ x,
             const float* __restrict__ eWih0, const float* __restrict__ eWhh0,
             const float* __restrict__ eBih0, const float* __restrict__ eBhh0,
             const float* __restrict__ eWih1, const float* __restrict__ eWhh1,
             const float* __restrict__ eBih1, const float* __restrict__ eBhh1,
             const float* __restrict__ dWih0, const float* __restrict__ dWhh0,
             const float* __restrict__ dBih0, const float* __restrict__ dBhh0,
             const float* __restrict__ dWih1, const float* __restrict__ dWhh1,
             const float* __restrict__ dBih1, const float* __restrict__ dBhh1,
             const float* __restrict__ Won, const float* __restrict__ bOn,
             const float* __restrict__ Wcv, const float* __restrict__ bCv,
             float* __restrict__ out, int L)
{
    extern __shared__ float sm[];
    const int tid  = threadIdx.x;
    const int g    = tid >> 6;
    const int j    = tid & 63;
    const int lane = tid & 31;
    const int w2   = (tid >> 5) & 1;

    /* -------- load encoder weights into SMEM -------- */
    for (int idx = tid; idx < 192 * 64; idx += NTHREADS) {
        int row = idx >> 6, k = idx & 63;
        sm[OFF_WHH0 + row * 68 + k] = eWhh0[idx];
        sm[OFF_WIH1 + row * 68 + k] = eWih1[idx];
        sm[OFF_WHH1 + row * 68 + k] = eWhh1[idx];
    }
    for (int idx = tid; idx < 3 * 6 * 64; idx += NTHREADS) {
        int jj = idx & 63, t2 = idx >> 6;
        int i = t2 % 6, gate = t2 / 6;
        sm[OFF_WIH0 + idx] = eWih0[(gate * 64 + jj) * NIN + i];
    }
    for (int idx = tid; idx < 192; idx += NTHREADS) {
        sm[OFF_BIH0 + idx] = eBih0[idx];
        sm[OFF_BHH0 + idx] = eBhh0[idx];
        sm[OFF_BIH1 + idx] = eBih1[idx];
        sm[OFF_BHH1 + idx] = eBhh1[idx];
    }
    for (int idx = tid; idx < ROWS * 64; idx += NTHREADS) {
        sm[OFF_H0 + idx] = 0.0f;
        sm[OFF_H1 + idx] = 0.0f;
    }
    __syncthreads();

    float b0r = sm[OFF_BIH0 + j] + sm[OFF_BHH0 + j];
    float b0z = sm[OFF_BIH0 + 64 + j] + sm[OFF_BHH0 + 64 + j];
    float b0in = sm[OFF_BIH0 + 128 + j];
    float b0hn = sm[OFF_BHH0 + 128 + j];
    float b1r = sm[OFF_BIH1 + j] + sm[OFF_BHH1 + j];
    float b1z = sm[OFF_BIH1 + 64 + j] + sm[OFF_BHH1 + 64 + j];
    float b1in = sm[OFF_BIH1 + 128 + j];
    float b1hn = sm[OFF_BHH1 + 128 + j];

    float h0[RR], h1[RR];
#pragma unroll
    for (int r = 0; r < RR; r++) { h0[r] = 0.0f; h1[r] = 0.0f; }

    const float* h0b = sm + OFF_H0 + g * RR * 64;
    const float* h1b = sm + OFF_H1 + g * RR * 64;

    /* ======================= encoder ======================= */
    for (int t = 0; t < TENC; t++) {
        for (int idx = tid; idx < ROWS * NIN; idx += NTHREADS) {
            int rl = idx / NIN, i = idx - rl * NIN;
            int row = blockIdx.x * ROWS + rl;
            if (row >= BTOT) row = BTOT - 1;
            sm[OFF_XS + rl * 8 + i] = x[row * (TENC * NIN) + t * NIN + i];
        }
        __syncthreads();

        float ar[RR], az[RR], ani[RR], anh[RR];

        /* layer-0: pass1 (r,z) */
        {
            u64 pr[RR], pz[RR];
#pragma unroll
            for (int r = 0; r < RR; r++) { pr[r] = 0ULL; pz[r] = 0ULL; }
            L0_PASS1(h0b);
#pragma unroll
            for (int r = 0; r < RR; r++) { ar[r] = f2red(pr[r]); az[r] = f2red(pz[r]); }
        }
        /* layer-0: pass2 (n hidden part) */
        {
            u64 pn[RR];
#pragma unroll
            for (int r = 0; r < RR; r++) pn[r] = 0ULL;
            L0_PASS2(h0b);
#pragma unroll
            for (int r = 0; r < RR; r++) anh[r] = f2red(pn[r]);
        }
#pragma unroll
        for (int r = 0; r < RR; r++) ani[r] = 0.0f;
#pragma unroll
        for (int i = 0; i < NIN; i++) {
            float wr = sm[OFF_WIH0 + i * 64 + j];
            float wz = sm[OFF_WIH0 + (6 + i) * 64 + j];
            float wn = sm[OFF_WIH0 + (12 + i) * 64 + j];
#pragma unroll
            for (int r = 0; r < RR; r++) {
                float xv = sm[OFF_XS + (g * RR + r) * 8 + i];
                ar[r] = fmaf(wr, xv, ar[r]);
                az[r] = fmaf(wz, xv, az[r]);
                ani[r] = fmaf(wn, xv, ani[r]);
            }
        }
#pragma unroll
        for (int r = 0; r < RR; r++) {
            float rg = sigf(ar[r] + b0r);
            float zg = sigf(az[r] + b0z);
            float ng = tanhf_(ani[r] + b0in + rg * (anh[r] + b0hn));
            h0[r] = ng + zg * (h0[r] - ng);
        }
        __syncthreads();
#pragma unroll
        for (int r = 0; r < RR; r++) sm[OFF_H0 + (g * RR + r) * 64 + j] = h0[r];
        __syncthreads();

        /* layer-1 fused */
        {
            u64 pr[RR], pz[RR];
#pragma unroll
            for (int r = 0; r < RR; r++) { pr[r] = 0ULL; pz[r] = 0ULL; }
            L1_PASS1();
#pragma unroll
            for (int r = 0; r < RR; r++) { ar[r] = f2red(pr[r]); az[r] = f2red(pz[r]); }
        }
        {
            u64 pni[RR], pnh[RR];
#pragma unroll
            for (int r = 0; r < RR; r++) { pni[r] = 0ULL; pnh[r] = 0ULL; }
            L1_PASS2();
#pragma unroll
            for (int r = 0; r < RR; r++) { ani[r] = f2red(pni[r]); anh[r] = f2red(pnh[r]); }
        }
#pragma unroll
        for (int r = 0; r < RR; r++) {
            float rg = sigf(ar[r] + b1r);
            float zg = sigf(az[r] + b1z);
            float ng = tanhf_(ani[r] + b1in + rg * (anh[r] + b1hn));
            h1[r] = ng + zg * (h1[r] - ng);
        }
        __syncthreads();   /* all layer-1 reads of h1s finished */
#pragma unroll
        for (int r = 0; r < RR; r++) sm[OFF_H1 + (g * RR + r) * 64 + j] = h1[r];
        /* visibility covered by first sync of next iteration / phase switch */
    }

    /* -------- swap in decoder weights -------- */
    __syncthreads();
    for (int idx = tid; idx < 192 * 64; idx += NTHREADS) {
        int row = idx >> 6, k = idx & 63;
        sm[OFF_WHH0 + row * 68 + k] = dWhh0[idx];
        sm[OFF_WIH1 + row * 68 + k] = dWih1[idx];
        sm[OFF_WHH1 + row * 68 + k] = dWhh1[idx];
    }
    for (int idx = tid; idx < 192; idx += NTHREADS) {
        sm[OFF_WIH0 + idx] = dWih0[idx];   /* [192][1] */
        sm[OFF_BIH0 + idx] = dBih0[idx];
        sm[OFF_BHH0 + idx] = dBhh0[idx];
        sm[OFF_BIH1 + idx] = dBih1[idx];
        sm[OFF_BHH1 + idx] = dBhh1[idx];
    }
    for (int idx = tid; idx < 64; idx += NTHREADS) {
        sm[OFF_WON + idx] = Won[idx];
        sm[OFF_WCV + idx] = Wcv[idx];
    }
    if (tid == 0) { sm[OFF_BON] = bOn[0]; sm[OFF_BCV] = bCv[0]; }
    for (int idx = tid; idx < ROWS; idx += NTHREADS) sm[OFF_PREV + idx] = 0.0f;
    __syncthreads();

    b0r = sm[OFF_BIH0 + j] + sm[OFF_BHH0 + j];
    b0z = sm[OFF_BIH0 + 64 + j] + sm[OFF_BHH0 + 64 + j];
    b0in = sm[OFF_BIH0 + 128 + j];
    b0hn = sm[OFF_BHH0 + 128 + j];
    b1r = sm[OFF_BIH1 + j] + sm[OFF_BHH1 + j];
    b1z = sm[OFF_BIH1 + 64 + j] + sm[OFF_BHH1 + 64 + j];
    b1in = sm[OFF_BIH1 + 128 + j];
    b1hn = sm[OFF_BHH1 + 128 + j];
    const float w0r = sm[OFF_WIH0 + j];
    const float w0z = sm[OFF_WIH0 + 64 + j];
    const float w0n = sm[OFF_WIH0 + 128 + j];
    const float won_ = sm[OFF_WON + j];
    const float wcv_ = sm[OFF_WCV + j];

    /* ======================= decoder ======================= */
    for (int t = 0; t < L; t++) {
        float ar[RR], az[RR], ani[RR], anh[RR];

        {
            u64 pr[RR], pz[RR];
#pragma unroll
            for (int r = 0; r < RR; r++) { pr[r] = 0ULL; pz[r] = 0ULL; }
            L0_PASS1(h0b);
#pragma unroll
            for (int r = 0; r < RR; r++) { ar[r] = f2red(pr[r]); az[r] = f2red(pz[r]); }
        }
        {
            u64 pn[RR];
#pragma unroll
            for (int r = 0; r < RR; r++) pn[r] = 0ULL;
            L0_PASS2(h0b);
#pragma unroll
            for (int r = 0; r < RR; r++) anh[r] = f2red(pn[r]);
        }
#pragma unroll
        for (int r = 0; r < RR; r++) {
            float pv = sm[OFF_PREV + g * RR + r];
            ar[r] = fmaf(w0r, pv, ar[r]);
            az[r] = fmaf(w0z, pv, az[r]);
            ani[r] = w0n * pv;
        }
#pragma unroll
        for (int r = 0; r < RR; r++) {
            float rg = sigf(ar[r] + b0r);
            float zg = sigf(az[r] + b0z);
            float ng = tanhf_(ani[r] + b0in + rg * (anh[r] + b0hn));
            h0[r] = ng + zg * (h0[r] - ng);
        }
        __syncthreads();
#pragma unroll
        for (int r = 0; r < RR; r++) sm[OFF_H0 + (g * RR + r) * 64 + j] = h0[r];
        __syncthreads();

        {
            u64 pr[RR], pz[RR];
#pragma unroll
            for (int r = 0; r < RR; r++) { pr[r] = 0ULL; pz[r] = 0ULL; }
            L1_PASS1();
#pragma unroll
            for (int r = 0; r < RR; r++) { ar[r] = f2red(pr[r]); az[r] = f2red(pz[r]); }
        }
        {
            u64 pni[RR], pnh[RR];
#pragma unroll
            for (int r = 0; r < RR; r++) { pni[r] = 0ULL; pnh[r] = 0ULL; }
            L1_PASS2();
#pragma unroll
            for (int r = 0; r < RR; r++) { ani[r] = f2red(pni[r]); anh[r] = f2red(pnh[r]); }
        }
#pragma unroll
        for (int r = 0; r < RR; r++) {
            float rg = sigf(ar[r] + b1r);
            float zg = sigf(az[r] + b1z);
            float ng = tanhf_(ani[r] + b1in + rg * (anh[r] + b1hn));
            h1[r] = ng + zg * (h1[r] - ng);
        }

        /* heads: dot(h1, Won/Wcv) reduced across the 64-thread group */
        float po[RR], pc[RR];
#pragma unroll
        for (int r = 0; r < RR; r++) { po[r] = won_ * h1[r]; pc[r] = wcv_ * h1[r]; }
#pragma unroll
        for (int r = 0; r < RR; r++) {
#pragma unroll
            for (int off = 16; off; off >>= 1) {
                po[r] += __shfl_xor_sync(0xffffffffu, po[r], off);
                pc[r] += __shfl_xor_sync(0xffffffffu, pc[r], off);
            }
        }
        if (lane == 0) {
#pragma unroll
            for (int r = 0; r < RR; r++) {
                sm[OFF_RED + (g * 4 + w2 * 2 + 0) * RR + r] = po[r];
                sm[OFF_RED + (g * 4 + w2 * 2 + 1) * RR + r] = pc[r];
            }
        }
        __syncthreads();   /* red visible; all layer-1 reads of h1s finished */
#pragma unroll
        for (int r = 0; r < RR; r++) sm[OFF_H1 + (g * RR + r) * 64 + j] = h1[r];

        if (j < RR) {
            int r = j;
            float oo = sm[OFF_RED + (g * 4 + 0) * RR + r] +
                       sm[OFF_RED + (g * 4 + 2) * RR + r] + sm[OFF_BON];
            float cc = sm[OFF_RED + (g * 4 + 1) * RR + r] +
                       sm[OFF_RED + (g * 4 + 3) * RR + r] + sm[OFF_BCV];
            float gated = (oo > 0.0f) ? cc : 0.0f;   /* sigmoid(oo) > 0.5 */
            sm[OFF_PREV + g * RR + r] = gated;
            int row = blockIdx.x * ROWS + g * RR + r;
            if (row < BTOT) out[row * L + t] = gated;
        }
        __syncthreads();   /* prev + h1s visible for next step */
    }
}

extern "C" void kernel_launch(void* const* d_in, const int* in_sizes, int n_in,
                              void* d_out, int out_size)
{
    const float* x     = (const float*)d_in[0];
    /* d_in[1] = target_len (device scalar) — derived from out_size instead */
    const float* eWih0 = (const float*)d_in[2];
    const float* eWhh0 = (const float*)d_in[3];
    const float* eBih0 = (const float*)d_in[4];
    const float* eBhh0 = (const float*)d_in[5];
    const float* eWih1 = (const float*)d_in[6];
    const float* eWhh1 = (const float*)d_in[7];
    const float* eBih1 = (const float*)d_in[8];
    const float* eBhh1 = (const float*)d_in[9];
    const float* dWih0 = (const float*)d_in[10];
    const float* dWhh0 = (const float*)d_in[11];
    const float* dBih0 = (const float*)d_in[12];
    const float* dBhh0 = (const float*)d_in[13];
    const float* dWih1 = (const float*)d_in[14];
    const float* dWhh1 = (const float*)d_in[15];
    const float* dBih1 = (const float*)d_in[16];
    const float* dBhh1 = (const float*)d_in[17];
    const float* Won   = (const float*)d_in[18];
    const float* bOn   = (const float*)d_in[19];
    const float* Wcv   = (const float*)d_in[20];
    const float* bCv   = (const float*)d_in[21];

    int L = out_size / BTOT;   /* 180 */

    cudaFuncSetAttribute(ccseq_kernel,
                         cudaFuncAttributeMaxDynamicSharedMemorySize, SMEM_BYTES);

    ccseq_kernel<<<NBLOCKS, NTHREADS, SMEM_BYTES>>>(
        x, eWih0, eWhh0, eBih0, eBhh0, eWih1, eWhh1, eBih1, eBhh1,
        dWih0, dWhh0, dBih0, dBhh0, dWih1, dWhh1, dBih1, dBhh1,
        Won, bOn, Wcv, bCv, (float*)d_out, L);
}

// round 12
// speedup vs baseline: 1.6898x; 1.6898x over previous
#include <cuda_runtime.h>

#define BTOT 16384
#define TENC 256
#define NTHREADS 512
#define ROWSB 128
#define NBLOCKS (BTOT / ROWSB)      /* 128 */
#define P0 84                       /* h0 buffer pitch: 84 mod 32 = 20 -> conflict-free */
#define P1 68                       /* h1 buffer pitch: 68 mod 32 = 4  -> conflict-free */

/* ---------------- shared memory layout (float offsets) ---------------- */
#define OB0 0                       /* GEMM0 B frags: 9*24*32 float2  = 13824 floats */
#define OB1 13824                   /* GEMM1 B frags: 16*24*32 float2 = 24576 floats */
#define OH0 38400                   /* h0 + aux: 128*84 = 10752 floats */
#define OH1 49152                   /* h1:       128*68 =  8704 floats */
#define SMEMF 57856
#define SMEM_BYTES (SMEMF * 4)      /* 231,424 B <= 227 KB opt-in */

__device__ __forceinline__ float tanhf_(float v) {
    float y; asm("tanh.approx.f32 %0, %1;" : "=f"(y) : "f"(v)); return y;
}
__device__ __forceinline__ float sigf(float v) {
    return fmaf(tanhf_(0.5f * v), 0.5f, 0.5f);
}
__device__ __forceinline__ unsigned cvt_tf32(float v) {
    unsigned r; asm("cvt.rna.tf32.f32 %0, %1;" : "=r"(r) : "f"(v)); return r;
}
__device__ __forceinline__ unsigned res_lo(float v, unsigned hi) {
    return __float_as_uint(v - __uint_as_float(hi));
}
__device__ __forceinline__ void mma_t(float* c, const unsigned* a, unsigned b0, unsigned b1) {
    asm volatile(
        "mma.sync.aligned.m16n8k8.row.col.f32.tf32.tf32.f32 "
        "{%0,%1,%2,%3}, {%4,%5,%6,%7}, {%8,%9}, {%0,%1,%2,%3};"
        : "+f"(c[0]), "+f"(c[1]), "+f"(c[2]), "+f"(c[3])
        : "r"(a[0]), "r"(a[1]), "r"(a[2]), "r"(a[3]), "r"(b0), "r"(b1));
}

/* one ktile: load 3 gate B-frags (r,z,n), then 4 mtiles of A, 9 HMMA per mtile */
#define KTILE(ABASE, APITCH, K0, BKT, NACC)                                       \
    do {                                                                          \
        unsigned bh0[3], bh1[3], bl0[3], bl1[3];                                  \
        _Pragma("unroll")                                                         \
        for (int q = 0; q < 3; q++) {                                             \
            float2 bv = *(const float2*)&sm[(BKT) + ((q * 8 + wn) * 32 + lane) * 2];\
            bh0[q] = cvt_tf32(bv.x); bl0[q] = res_lo(bv.x, bh0[q]);               \
            bh1[q] = cvt_tf32(bv.y); bl1[q] = res_lo(bv.y, bh1[q]);               \
        }                                                                         \
        _Pragma("unroll")                                                         \
        for (int mt = 0; mt < 4; mt++) {                                          \
            int r0 = (ABASE) + (mtb0 + mt * 16 + grp) * (APITCH) + (K0) + tg;     \
            int r1 = r0 + 8 * (APITCH);                                           \
            float v0 = sm[r0], v1 = sm[r1], v2 = sm[r0 + 4], v3 = sm[r1 + 4];     \
            unsigned ah[4], al[4];                                                \
            ah[0] = cvt_tf32(v0); al[0] = res_lo(v0, ah[0]);                      \
            ah[1] = cvt_tf32(v1); al[1] = res_lo(v1, ah[1]);                      \
            ah[2] = cvt_tf32(v2); al[2] = res_lo(v2, ah[2]);                      \
            ah[3] = cvt_tf32(v3); al[3] = res_lo(v3, ah[3]);                      \
            mma_t(aR[mt], ah, bh0[0], bh1[0]);                                    \
            mma_t(aR[mt], al, bh0[0], bh1[0]);                                    \
            mma_t(aR[mt], ah, bl0[0], bl1[0]);                                    \
            mma_t(aZ[mt], ah, bh0[1], bh1[1]);                                    \
            mma_t(aZ[mt], al, bh0[1], bh1[1]);                                    \
            mma_t(aZ[mt], ah, bl0[1], bl1[1]);                                    \
            mma_t(NACC[mt], ah, bh0[2], bh1[2]);                                  \
            mma_t(NACC[mt], al, bh0[2], bh1[2]);                                  \
            mma_t(NACC[mt], ah, bl0[2], bl1[2]);                                  \
        }                                                                         \
    } while (0)

#define ZACC                                                                      \
    do {                                                                          \
        _Pragma("unroll") for (int mt = 0; mt < 4; mt++)                          \
        _Pragma("unroll") for (int p = 0; p < 4; p++) {                           \
            aR[mt][p] = 0.f; aZ[mt][p] = 0.f; aNi[mt][p] = 0.f; aNh[mt][p] = 0.f; \
        }                                                                         \
    } while (0)

/* gates + hidden update; C frag rows = grp/grp+8, cols = 2tg/2tg+1 of ntile */
#define GATES(HBASE, HPITCH, BR, BZ, BI, BH)                                      \
    do {                                                                          \
        _Pragma("unroll")                                                         \
        for (int mt = 0; mt < 4; mt++) {                                          \
            _Pragma("unroll")                                                     \
            for (int pr = 0; pr < 2; pr++) {                                      \
                int row = mtb0 + mt * 16 + grp + pr * 8;                          \
                int off = (HBASE) + row * (HPITCH) + jc;                          \
                float2 hold = *(const float2*)&sm[off];                           \
                float rg0 = sigf(aR[mt][pr * 2 + 0] + BR[0]);                     \
                float zg0 = sigf(aZ[mt][pr * 2 + 0] + BZ[0]);                     \
                float ng0 = tanhf_(aNi[mt][pr * 2 + 0] + BI[0] +                  \
                                   rg0 * (aNh[mt][pr * 2 + 0] + BH[0]));          \
                float rg1 = sigf(aR[mt][pr * 2 + 1] + BR[1]);                     \
                float zg1 = sigf(aZ[mt][pr * 2 + 1] + BZ[1]);                     \
                float ng1 = tanhf_(aNi[mt][pr * 2 + 1] + BI[1] +                  \
                                   rg1 * (aNh[mt][pr * 2 + 1] + BH[1]));          \
                float2 hn;                                                        \
                hn.x = ng0 + zg0 * (hold.x - ng0);                                \
                hn.y = ng1 + zg1 * (hold.y - ng1);                                \
                *(float2*)&sm[off] = hn;                                          \
            }                                                                     \
        }                                                                         \
    } while (0)

/* fill B fragment buffers for one phase (encoder or decoder weights) */
#define FILLB(WHH0, WIH0, IH0C, WIH1, WHH1)                                       \
    do {                                                                          \
        for (int idx = tid; idx < 9 * 768; idx += NTHREADS) {                     \
            int ln = idx & 31, nt = (idx >> 5) % 24, kt = idx / 768;              \
            int g2 = ln >> 2, t2 = ln & 3, n = nt * 8 + g2;                       \
            float v0, v1;                                                         \
            if (kt < 8) {                                                         \
                v0 = (WHH0)[n * 64 + kt * 8 + t2];                                \
                v1 = (WHH0)[n * 64 + kt * 8 + t2 + 4];                            \
            } else {                                                              \
                v0 = (t2 < (IH0C)) ? (WIH0)[n * (IH0C) + t2] : 0.f;               \
                v1 = (t2 + 4 < (IH0C)) ? (WIH0)[n * (IH0C) + t2 + 4] : 0.f;       \
            }                                                                     \
            sm[OB0 + idx * 2] = v0; sm[OB0 + idx * 2 + 1] = v1;                   \
        }                                                                         \
        for (int idx = tid; idx < 16 * 768; idx += NTHREADS) {                    \
            int ln = idx & 31, nt = (idx >> 5) % 24, kt = idx / 768;              \
            int g2 = ln >> 2, t2 = ln & 3, n = nt * 8 + g2;                       \
            float v0, v1;                                                         \
            if (kt < 8) {                                                         \
                v0 = (WIH1)[n * 64 + kt * 8 + t2];                                \
                v1 = (WIH1)[n * 64 + kt * 8 + t2 + 4];                            \
            } else {                                                              \
                v0 = (WHH1)[n * 64 + (kt - 8) * 8 + t2];                          \
                v1 = (WHH1)[n * 64 + (kt - 8) * 8 + t2 + 4];                      \
            }                                                                     \
            sm[OB1 + idx * 2] = v0; sm[OB1 + idx * 2 + 1] = v1;                   \
        }                                                                         \
    } while (0)

#define LOADBIAS(BIH, BHH, BR, BZ, BI, BH)                                        \
    do {                                                                          \
        BR[0] = (BIH)[jc] + (BHH)[jc];                                            \
        BR[1] = (BIH)[jc + 1] + (BHH)[jc + 1];                                    \
        BZ[0] = (BIH)[64 + jc] + (BHH)[64 + jc];                                  \
        BZ[1] = (BIH)[65 + jc] + (BHH)[65 + jc];                                  \
        BI[0] = (BIH)[128 + jc]; BI[1] = (BIH)[129 + jc];                         \
        BH[0] = (BHH)[128 + jc]; BH[1] = (BHH)[129 + jc];                         \
    } while (0)

__global__ void __launch_bounds__(NTHREADS, 1)
ccseq_tc(const float* __restrict__ x,
         const float* __restrict__ eWih0, const float* __restrict__ eWhh0,
         const float* __restrict__ eBih0, const float* __restrict__ eBhh0,
         const float* __restrict__ eWih1, const float* __restrict__ eWhh1,
         const float* __restrict__ eBih1, const float* __restrict__ eBhh1,
         const float* __restrict__ dWih0, const float* __restrict__ dWhh0,
         const float* __restrict__ dBih0, const float* __restrict__ dBhh0,
         const float* __restrict__ dWih1, const float* __restrict__ dWhh1,
         const float* __restrict__ dBih1, const float* __restrict__ dBhh1,
         const float* __restrict__ Won, const float* __restrict__ bOn,
         const float* __restrict__ Wcv, const float* __restrict__ bCv,
         float* __restrict__ out, int L)
{
    extern __shared__ float sm[];
    const int tid  = threadIdx.x;
    const int lane = tid & 31;
    const int warp = tid >> 5;
    const int grp  = lane >> 2, tg = lane & 3;
    const int wm   = warp >> 3, wn = warp & 7;
    const int mtb0 = wm * 64;
    const int jc   = wn * 8 + 2 * tg;
    const int blk  = blockIdx.x;

    FILLB(eWhh0, eWih0, 6, eWih1, eWhh1);
    for (int idx = tid; idx < 128 * P0; idx += NTHREADS) sm[OH0 + idx] = 0.f;
    for (int idx = tid; idx < 128 * P1; idx += NTHREADS) sm[OH1 + idx] = 0.f;

    float b0r[2], b0z[2], b0i[2], b0h[2], b1r[2], b1z[2], b1i[2], b1h[2];
    LOADBIAS(eBih0, eBhh0, b0r, b0z, b0i, b0h);
    LOADBIAS(eBih1, eBhh1, b1r, b1z, b1i, b1h);
    __syncthreads();

    float aR[4][4], aZ[4][4], aNi[4][4], aNh[4][4];

    /* ======================= encoder ======================= */
    for (int t = 0; t < TENC; t++) {
        for (int idx = tid; idx < 768; idx += NTHREADS) {
            int r = idx / 6, i = idx - r * 6;
            sm[OH0 + r * P0 + 64 + i] = x[((blk * 128 + r) * 256 + t) * 6 + i];
        }
        __syncthreads();

        ZACC;
#pragma unroll 1
        for (int kt = 0; kt < 8; kt++) KTILE(OH0, P0, kt * 8, OB0 + kt * 1536, aNh);
        KTILE(OH0, P0, 64, OB0 + 8 * 1536, aNi);   /* aux: x @ Wih0^T */
        __syncthreads();
        GATES(OH0, P0, b0r, b0z, b0i, b0h);
        __syncthreads();

        ZACC;
#pragma unroll 1
        for (int kt = 0; kt < 8; kt++) KTILE(OH0, P0, kt * 8, OB1 + kt * 1536, aNi);
#pragma unroll 1
        for (int kt = 0; kt < 8; kt++) KTILE(OH1, P1, kt * 8, OB1 + (8 + kt) * 1536, aNh);
        __syncthreads();
        GATES(OH1, P1, b1r, b1z, b1i, b1h);
        __syncthreads();
    }

    /* ---------------- swap to decoder weights ---------------- */
    FILLB(dWhh0, dWih0, 1, dWih1, dWhh1);
    LOADBIAS(dBih0, dBhh0, b0r, b0z, b0i, b0h);
    LOADBIAS(dBih1, dBhh1, b1r, b1z, b1i, b1h);
    if (tid < 128) sm[OH0 + tid * P0 + 64] = 0.f;   /* prev = 0 */
    const float bon = bOn[0], bcv = bCv[0];
    const int hrow = tid >> 2, hq = tid & 3;
    __syncthreads();

    /* ======================= decoder ======================= */
    for (int t = 0; t < L; t++) {
        ZACC;
#pragma unroll 1
        for (int kt = 0; kt < 8; kt++) KTILE(OH0, P0, kt * 8, OB0 + kt * 1536, aNh);
        KTILE(OH0, P0, 64, OB0 + 8 * 1536, aNi);   /* aux: prev * Wih0 */
        __syncthreads();
        GATES(OH0, P0, b0r, b0z, b0i, b0h);
        __syncthreads();

        ZACC;
#pragma unroll 1
        for (int kt = 0; kt < 8; kt++) KTILE(OH0, P0, kt * 8, OB1 + kt * 1536, aNi);
#pragma unroll 1
        for (int kt = 0; kt < 8; kt++) KTILE(OH1, P1, kt * 8, OB1 + (8 + kt) * 1536, aNh);
        __syncthreads();
        GATES(OH1, P1, b1r, b1z, b1i, b1h);
        __syncthreads();

        /* heads: 4 threads per row, 16 cols each, shfl-reduce over q */
        {
            const float* hp = &sm[OH1 + hrow * P1 + hq * 16];
            float po = 0.f, pc = 0.f;
#pragma unroll
            for (int u = 0; u < 16; u++) {
                float hv = hp[u];
                po = fmaf(hv, Won[hq * 16 + u], po);
                pc = fmaf(hv, Wcv[hq * 16 + u], pc);
            }
            po += __shfl_xor_sync(0xffffffffu, po, 1);
            po += __shfl_xor_sync(0xffffffffu, po, 2);
            pc += __shfl_xor_sync(0xffffffffu, pc, 1);
            pc += __shfl_xor_sync(0xffffffffu, pc, 2);
            if (hq == 0) {
                float gated = (po + bon > 0.f) ? (pc + bcv) : 0.f;
                sm[OH0 + hrow * P0 + 64] = gated;      /* prev for next step */
                out[(blk * 128 + hrow) * L + t] = gated;
            }
        }
        __syncthreads();
    }
}

extern "C" void kernel_launch(void* const* d_in, const int* in_sizes, int n_in,
                              void* d_out, int out_size)
{
    const float* x     = (const float*)d_in[0];
    /* d_in[1] = target_len (device scalar) — derived from out_size instead */
    const float* eWih0 = (const float*)d_in[2];
    const float* eWhh0 = (const float*)d_in[3];
    const float* eBih0 = (const float*)d_in[4];
    const float* eBhh0 = (const float*)d_in[5];
    const float* eWih1 = (const float*)d_in[6];
    const float* eWhh1 = (const float*)d_in[7];
    const float* eBih1 = (const float*)d_in[8];
    const float* eBhh1 = (const float*)d_in[9];
    const float* dWih0 = (const float*)d_in[10];
    const float* dWhh0 = (const float*)d_in[11];
    const float* dBih0 = (const float*)d_in[12];
    const float* dBhh0 = (const float*)d_in[13];
    const float* dWih1 = (const float*)d_in[14];
    const float* dWhh1 = (const float*)d_in[15];
    const float* dBih1 = (const float*)d_in[16];
    const float* dBhh1 = (const float*)d_in[17];
    const float* Won   = (const float*)d_in[18];
    const float* bOn   = (const float*)d_in[19];
    const float* Wcv   = (const float*)d_in[20];
    const float* bCv   = (const float*)d_in[21];

    int L = out_size / BTOT;   /* 180 */

    cudaFuncSetAttribute(ccseq_tc,
                         cudaFuncAttributeMaxDynamicSharedMemorySize, SMEM_BYTES);

    ccseq_tc<<<NBLOCKS, NTHREADS, SMEM_BYTES>>>(
        x, eWih0, eWhh0, eBih0, eBhh0, eWih1, eWhh1, eBih1, eBhh1,
        dWih0, dWhh0, dBih0, dBhh0, dWih1, dWhh1, dBih1, dBhh1,
        Won, bOn, Wcv, bCv, (float*)d_out, L);
}